// round 1
// baseline (speedup 1.0000x reference)
#include <cuda_runtime.h>
#include <math.h>

#define NB 8
#define SS 2048
#define DD 1024
#define AA 512
#define DVV 512

// Scratch for the three projections (allocation-free rule: __device__ globals)
__device__ float g_Qp[(size_t)NB * SS * AA];
__device__ float g_Kp[(size_t)NB * SS * AA];
__device__ float g_WV[(size_t)NB * SS * DVV];

// ---------------------------------------------------------------------------
// NT GEMM + bias: C[M,N] = A[M,K] * B[N,K]^T + bias[N]
// 128x128 block, BK=16, 256 threads, 8x8 per thread. All dims divide tiles.
// ---------------------------------------------------------------------------
__global__ __launch_bounds__(256, 2)
void gemm_nt_bias(const float* __restrict__ Am, const float* __restrict__ Bm,
                  const float* __restrict__ bias, float* __restrict__ C,
                  int M, int N, int K)
{
    __shared__ float As[16][128];
    __shared__ float Bs[16][128];
    const int tid = threadIdx.x;
    const int m0 = blockIdx.y * 128;
    const int n0 = blockIdx.x * 128;
    const int tx = tid & 15, ty = tid >> 4;

    float acc[8][8];
#pragma unroll
    for (int i = 0; i < 8; i++)
#pragma unroll
        for (int j = 0; j < 8; j++) acc[i][j] = 0.f;

    for (int k0 = 0; k0 < K; k0 += 16) {
#pragma unroll
        for (int l = 0; l < 2; l++) {
            int f = tid + l * 256;
            int row = f >> 2;
            int c4 = (f & 3) * 4;
            float4 av = *reinterpret_cast<const float4*>(&Am[(size_t)(m0 + row) * K + k0 + c4]);
            As[c4 + 0][row] = av.x; As[c4 + 1][row] = av.y;
            As[c4 + 2][row] = av.z; As[c4 + 3][row] = av.w;
            float4 bv = *reinterpret_cast<const float4*>(&Bm[(size_t)(n0 + row) * K + k0 + c4]);
            Bs[c4 + 0][row] = bv.x; Bs[c4 + 1][row] = bv.y;
            Bs[c4 + 2][row] = bv.z; Bs[c4 + 3][row] = bv.w;
        }
        __syncthreads();
#pragma unroll
        for (int kk = 0; kk < 16; kk++) {
            float a[8], b[8];
            *reinterpret_cast<float4*>(&a[0]) = *reinterpret_cast<const float4*>(&As[kk][ty * 8]);
            *reinterpret_cast<float4*>(&a[4]) = *reinterpret_cast<const float4*>(&As[kk][ty * 8 + 4]);
            *reinterpret_cast<float4*>(&b[0]) = *reinterpret_cast<const float4*>(&Bs[kk][tx * 8]);
            *reinterpret_cast<float4*>(&b[4]) = *reinterpret_cast<const float4*>(&Bs[kk][tx * 8 + 4]);
#pragma unroll
            for (int i = 0; i < 8; i++)
#pragma unroll
                for (int j = 0; j < 8; j++)
                    acc[i][j] = fmaf(a[i], b[j], acc[i][j]);
        }
        __syncthreads();
    }
    float bvv[8];
#pragma unroll
    for (int j = 0; j < 8; j++) bvv[j] = bias[n0 + tx * 8 + j];
#pragma unroll
    for (int i = 0; i < 8; i++) {
        size_t off = (size_t)(m0 + ty * 8 + i) * N + n0 + tx * 8;
#pragma unroll
        for (int jj = 0; jj < 8; jj += 4) {
            float4 v = make_float4(acc[i][jj] + bvv[jj], acc[i][jj + 1] + bvv[jj + 1],
                                   acc[i][jj + 2] + bvv[jj + 2], acc[i][jj + 3] + bvv[jj + 3]);
            *reinterpret_cast<float4*>(&C[off + jj]) = v;
        }
    }
}

// ---------------------------------------------------------------------------
// Scores, pre-transposed: C[b, k, q] = scale * Kp[b,k]·Qp[b,q] - 1e9*mask[b,q,k]
// (NT GEMM per batch with mask epilogue; writes directly into attn output slot)
// ---------------------------------------------------------------------------
__global__ __launch_bounds__(256, 2)
void scores_kernel(const float* __restrict__ Kp, const float* __restrict__ Qp,
                   const int* __restrict__ maskB, float* __restrict__ Cb)
{
    __shared__ float As[16][128];
    __shared__ float Bs[16][128];
    const int tid = threadIdx.x;
    const int m0 = blockIdx.y * 128;   // k index
    const int n0 = blockIdx.x * 128;   // q index
    const int tx = tid & 15, ty = tid >> 4;
    const float* Am = Kp + (size_t)blockIdx.z * SS * AA;
    const float* Bm = Qp + (size_t)blockIdx.z * SS * AA;
    const int* mk = maskB + (size_t)blockIdx.z * SS * SS;
    float* C = Cb + (size_t)blockIdx.z * SS * SS;

    float acc[8][8];
#pragma unroll
    for (int i = 0; i < 8; i++)
#pragma unroll
        for (int j = 0; j < 8; j++) acc[i][j] = 0.f;

    for (int k0 = 0; k0 < AA; k0 += 16) {
#pragma unroll
        for (int l = 0; l < 2; l++) {
            int f = tid + l * 256;
            int row = f >> 2;
            int c4 = (f & 3) * 4;
            float4 av = *reinterpret_cast<const float4*>(&Am[(size_t)(m0 + row) * AA + k0 + c4]);
            As[c4 + 0][row] = av.x; As[c4 + 1][row] = av.y;
            As[c4 + 2][row] = av.z; As[c4 + 3][row] = av.w;
            float4 bv = *reinterpret_cast<const float4*>(&Bm[(size_t)(n0 + row) * AA + k0 + c4]);
            Bs[c4 + 0][row] = bv.x; Bs[c4 + 1][row] = bv.y;
            Bs[c4 + 2][row] = bv.z; Bs[c4 + 3][row] = bv.w;
        }
        __syncthreads();
#pragma unroll
        for (int kk = 0; kk < 16; kk++) {
            float a[8], b[8];
            *reinterpret_cast<float4*>(&a[0]) = *reinterpret_cast<const float4*>(&As[kk][ty * 8]);
            *reinterpret_cast<float4*>(&a[4]) = *reinterpret_cast<const float4*>(&As[kk][ty * 8 + 4]);
            *reinterpret_cast<float4*>(&b[0]) = *reinterpret_cast<const float4*>(&Bs[kk][tx * 8]);
            *reinterpret_cast<float4*>(&b[4]) = *reinterpret_cast<const float4*>(&Bs[kk][tx * 8 + 4]);
#pragma unroll
            for (int i = 0; i < 8; i++)
#pragma unroll
                for (int j = 0; j < 8; j++)
                    acc[i][j] = fmaf(a[i], b[j], acc[i][j]);
        }
        __syncthreads();
    }

    const float scale = 0.04419417382415922f;  // 1/sqrt(512)
#pragma unroll
    for (int j = 0; j < 8; j++) {
        // mask[b, q=n, k=m]; m-direction contiguous -> int4 loads
        size_t base = (size_t)(n0 + tx * 8 + j) * SS + m0 + ty * 8;
        int4 ma = *reinterpret_cast<const int4*>(&mk[base]);
        int4 mb = *reinterpret_cast<const int4*>(&mk[base + 4]);
        float mf0 = (float)ma.x, mf1 = (float)ma.y, mf2 = (float)ma.z, mf3 = (float)ma.w;
        float mf4 = (float)mb.x, mf5 = (float)mb.y, mf6 = (float)mb.z, mf7 = (float)mb.w;
        acc[0][j] = acc[0][j] * scale - 1e9f * mf0;
        acc[1][j] = acc[1][j] * scale - 1e9f * mf1;
        acc[2][j] = acc[2][j] * scale - 1e9f * mf2;
        acc[3][j] = acc[3][j] * scale - 1e9f * mf3;
        acc[4][j] = acc[4][j] * scale - 1e9f * mf4;
        acc[5][j] = acc[5][j] * scale - 1e9f * mf5;
        acc[6][j] = acc[6][j] * scale - 1e9f * mf6;
        acc[7][j] = acc[7][j] * scale - 1e9f * mf7;
    }
#pragma unroll
    for (int i = 0; i < 8; i++) {
        size_t off = (size_t)(m0 + ty * 8 + i) * SS + n0 + tx * 8;
#pragma unroll
        for (int jj = 0; jj < 8; jj += 4) {
            *reinterpret_cast<float4*>(&C[off + jj]) =
                make_float4(acc[i][jj], acc[i][jj + 1], acc[i][jj + 2], acc[i][jj + 3]);
        }
    }
}

// ---------------------------------------------------------------------------
// In-place row softmax over rows of length SS=2048. One block (256 thr) per row.
// ---------------------------------------------------------------------------
__global__ void softmax_rows(float* __restrict__ p)
{
    __shared__ float red[33];
    float* x = p + (size_t)blockIdx.x * SS;
    int tid = threadIdx.x;
    float v[8];
    float mx = -1e30f;
#pragma unroll
    for (int i = 0; i < 8; i++) { v[i] = x[tid + i * 256]; mx = fmaxf(mx, v[i]); }
#pragma unroll
    for (int o = 16; o > 0; o >>= 1) mx = fmaxf(mx, __shfl_xor_sync(0xffffffffu, mx, o));
    if ((tid & 31) == 0) red[tid >> 5] = mx;
    __syncthreads();
    if (tid < 32) {
        float m = (tid < 8) ? red[tid] : -1e30f;
#pragma unroll
        for (int o = 4; o > 0; o >>= 1) m = fmaxf(m, __shfl_xor_sync(0xffffffffu, m, o));
        if (tid == 0) red[32] = m;
    }
    __syncthreads();
    mx = red[32];
    float s = 0.f;
#pragma unroll
    for (int i = 0; i < 8; i++) { v[i] = __expf(v[i] - mx); s += v[i]; }
#pragma unroll
    for (int o = 16; o > 0; o >>= 1) s += __shfl_xor_sync(0xffffffffu, s, o);
    if ((tid & 31) == 0) red[tid >> 5] = s;
    __syncthreads();
    if (tid < 32) {
        float m = (tid < 8) ? red[tid] : 0.f;
#pragma unroll
        for (int o = 4; o > 0; o >>= 1) m += __shfl_xor_sync(0xffffffffu, m, o);
        if (tid == 0) red[32] = m;
    }
    __syncthreads();
    float inv = 1.0f / red[32];
#pragma unroll
    for (int i = 0; i < 8; i++) x[tid + i * 256] = v[i] * inv;
}

// ---------------------------------------------------------------------------
// Batched NN GEMM: C[b][M,N] = A[b][M,K] * B[b][K,N]
// ---------------------------------------------------------------------------
__global__ __launch_bounds__(256, 2)
void gemm_nn_batched(const float* __restrict__ Ab, const float* __restrict__ Bbm,
                     float* __restrict__ Cb, int M, int N, int K)
{
    __shared__ float As[16][128];
    __shared__ float Bs[16][128];
    const int tid = threadIdx.x;
    const int m0 = blockIdx.y * 128;
    const int n0 = blockIdx.x * 128;
    const int tx = tid & 15, ty = tid >> 4;
    const float* Am = Ab + (size_t)blockIdx.z * M * K;
    const float* Bm = Bbm + (size_t)blockIdx.z * K * N;
    float* C = Cb + (size_t)blockIdx.z * M * N;

    float acc[8][8];
#pragma unroll
    for (int i = 0; i < 8; i++)
#pragma unroll
        for (int j = 0; j < 8; j++) acc[i][j] = 0.f;

    for (int k0 = 0; k0 < K; k0 += 16) {
#pragma unroll
        for (int l = 0; l < 2; l++) {
            int f = tid + l * 256;
            {
                int row = f >> 2;
                int c4 = (f & 3) * 4;
                float4 av = *reinterpret_cast<const float4*>(&Am[(size_t)(m0 + row) * K + k0 + c4]);
                As[c4 + 0][row] = av.x; As[c4 + 1][row] = av.y;
                As[c4 + 2][row] = av.z; As[c4 + 3][row] = av.w;
            }
            {
                int row = f >> 5;           // 0..15
                int cc = (f & 31) * 4;      // 0..124
                float4 bv = *reinterpret_cast<const float4*>(&Bm[(size_t)(k0 + row) * N + n0 + cc]);
                *reinterpret_cast<float4*>(&Bs[row][cc]) = bv;
            }
        }
        __syncthreads();
#pragma unroll
        for (int kk = 0; kk < 16; kk++) {
            float a[8], b[8];
            *reinterpret_cast<float4*>(&a[0]) = *reinterpret_cast<const float4*>(&As[kk][ty * 8]);
            *reinterpret_cast<float4*>(&a[4]) = *reinterpret_cast<const float4*>(&As[kk][ty * 8 + 4]);
            *reinterpret_cast<float4*>(&b[0]) = *reinterpret_cast<const float4*>(&Bs[kk][tx * 8]);
            *reinterpret_cast<float4*>(&b[4]) = *reinterpret_cast<const float4*>(&Bs[kk][tx * 8 + 4]);
#pragma unroll
            for (int i = 0; i < 8; i++)
#pragma unroll
                for (int j = 0; j < 8; j++)
                    acc[i][j] = fmaf(a[i], b[j], acc[i][j]);
        }
        __syncthreads();
    }
#pragma unroll
    for (int i = 0; i < 8; i++) {
        size_t off = (size_t)(m0 + ty * 8 + i) * N + n0 + tx * 8;
#pragma unroll
        for (int jj = 0; jj < 8; jj += 4) {
            *reinterpret_cast<float4*>(&C[off + jj]) =
                make_float4(acc[i][jj], acc[i][jj + 1], acc[i][jj + 2], acc[i][jj + 3]);
        }
    }
}

// ---------------------------------------------------------------------------
extern "C" void kernel_launch(void* const* d_in, const int* in_sizes, int n_in,
                              void* d_out, int out_size)
{
    const float* Q    = (const float*)d_in[0];
    const float* K    = (const float*)d_in[1];
    const float* V    = (const float*)d_in[2];
    const int*   mask = (const int*)  d_in[3];
    const float* Wq   = (const float*)d_in[4];
    const float* bq   = (const float*)d_in[5];
    const float* Wk   = (const float*)d_in[6];
    const float* bk   = (const float*)d_in[7];
    const float* Wv   = (const float*)d_in[8];
    const float* bv   = (const float*)d_in[9];

    float* out  = (float*)d_out;                      // selfOutput [B,S,Dv]
    float* attn = out + (size_t)NB * SS * DVV;        // attn       [B,S,S]

    static float *pQp = nullptr, *pKp = nullptr, *pWV = nullptr;
    if (!pQp) {
        cudaGetSymbolAddress((void**)&pQp, g_Qp);
        cudaGetSymbolAddress((void**)&pKp, g_Kp);
        cudaGetSymbolAddress((void**)&pWV, g_WV);
    }

    dim3 blk(256);

    // Projections: [B*S, D] x [A, D]^T
    dim3 gproj(AA / 128, (NB * SS) / 128);
    gemm_nt_bias<<<gproj, blk>>>(Q, Wq, bq, pQp, NB * SS, AA, DD);
    gemm_nt_bias<<<gproj, blk>>>(K, Wk, bk, pKp, NB * SS, AA, DD);
    gemm_nt_bias<<<gproj, blk>>>(V, Wv, bv, pWV, NB * SS, DVV, DD);

    // Pre-transposed masked scores -> attn slot
    dim3 gsc(SS / 128, SS / 128, NB);
    scores_kernel<<<gsc, blk>>>(pKp, pQp, mask, attn);

    // Row softmax in place
    softmax_rows<<<NB * SS, 256>>>(attn);

    // selfOutput = attn @ WV
    dim3 gout(DVV / 128, SS / 128, NB);
    gemm_nn_batched<<<gout, blk>>>(attn, pWV, out, SS, DVV, SS);
}

// round 3
// speedup vs baseline: 1.9328x; 1.9328x over previous
#include <cuda_runtime.h>
#include <cuda_bf16.h>
#include <cstdint>

#define NB 8
#define SS 2048
#define DD 1024
#define AA 512
#define DVV 512

// GEMM tiling
#define BM 128
#define BN 128
#define BKC 64
#define PADK 72                      // bf16 row stride (64 + 8 pad)
#define PLANE (128 * PADK * 2)       // 18432 bytes per operand plane
#define SMEM_GEMM (4 * PLANE)        // 73728 bytes

// ---------------------------------------------------------------------------
// Scratch: bf16 hi/lo split operands
// ---------------------------------------------------------------------------
__device__ __nv_bfloat16 g_QpHi[(size_t)NB * SS * AA];
__device__ __nv_bfloat16 g_QpLo[(size_t)NB * SS * AA];
__device__ __nv_bfloat16 g_KpHi[(size_t)NB * SS * AA];
__device__ __nv_bfloat16 g_KpLo[(size_t)NB * SS * AA];
__device__ __nv_bfloat16 g_WVTHi[(size_t)NB * DVV * SS];   // [b][v][s]
__device__ __nv_bfloat16 g_WVTLo[(size_t)NB * DVV * SS];

// ---------------------------------------------------------------------------
// Helpers
// ---------------------------------------------------------------------------
__device__ __forceinline__ uint32_t smem_u32(const void* p) {
    uint32_t a;
    asm("{ .reg .u64 t; cvta.to.shared.u64 t, %1; cvt.u32.u64 %0, t; }" : "=r"(a) : "l"(p));
    return a;
}

__device__ __forceinline__ void ldsm4(uint32_t (&r)[4], uint32_t addr) {
    asm volatile("ldmatrix.sync.aligned.m8n8.x4.shared.b16 {%0,%1,%2,%3}, [%4];"
        : "=r"(r[0]), "=r"(r[1]), "=r"(r[2]), "=r"(r[3]) : "r"(addr));
}

__device__ __forceinline__ void mma_bf16(float* d, const uint32_t* a, uint32_t b0, uint32_t b1) {
    asm volatile("mma.sync.aligned.m16n8k16.row.col.f32.bf16.bf16.f32 "
        "{%0,%1,%2,%3}, {%4,%5,%6,%7}, {%8,%9}, {%0,%1,%2,%3};"
        : "+f"(d[0]), "+f"(d[1]), "+f"(d[2]), "+f"(d[3])
        : "r"(a[0]), "r"(a[1]), "r"(a[2]), "r"(a[3]), "r"(b0), "r"(b1));
}

__device__ __forceinline__ void split2(float a, float b, uint32_t& hi, uint32_t& lo) {
    __nv_bfloat16 ah = __float2bfloat16_rn(a);
    __nv_bfloat16 bh = __float2bfloat16_rn(b);
    __nv_bfloat16 al = __float2bfloat16_rn(a - __bfloat162float(ah));
    __nv_bfloat16 bl = __float2bfloat16_rn(b - __bfloat162float(bh));
    hi = (uint32_t)__bfloat16_as_ushort(ah) | ((uint32_t)__bfloat16_as_ushort(bh) << 16);
    lo = (uint32_t)__bfloat16_as_ushort(al) | ((uint32_t)__bfloat16_as_ushort(bl) << 16);
}

// fp32 source row: 32 floats -> split -> hi/lo planes (16B stores)
__device__ __forceinline__ void load_split32(const float* __restrict__ s,
                                             char* dhi, char* dlo) {
#pragma unroll
    for (int g = 0; g < 4; g++) {
        float4 v0 = *reinterpret_cast<const float4*>(s + g * 8);
        float4 v1 = *reinterpret_cast<const float4*>(s + g * 8 + 4);
        uint32_t h0, h1, h2, h3, l0, l1, l2, l3;
        split2(v0.x, v0.y, h0, l0); split2(v0.z, v0.w, h1, l1);
        split2(v1.x, v1.y, h2, l2); split2(v1.z, v1.w, h3, l3);
        *reinterpret_cast<uint4*>(dhi + g * 16) = make_uint4(h0, h1, h2, h3);
        *reinterpret_cast<uint4*>(dlo + g * 16) = make_uint4(l0, l1, l2, l3);
    }
}
// bf16 pre-split source: copy 32 bf16 each of hi/lo
__device__ __forceinline__ void load_copy32(const __nv_bfloat16* __restrict__ sh,
                                            const __nv_bfloat16* __restrict__ sl,
                                            char* dhi, char* dlo) {
#pragma unroll
    for (int g = 0; g < 4; g++) {
        *reinterpret_cast<uint4*>(dhi + g * 16) = reinterpret_cast<const uint4*>(sh)[g];
        *reinterpret_cast<uint4*>(dlo + g * 16) = reinterpret_cast<const uint4*>(sl)[g];
    }
}

// ---------------------------------------------------------------------------
// One BK=64 chunk of bf16x3 MMA. aoff[4]/boff[2] are per-lane byte offsets
// into a plane (row+khalf encoded). Planes: Ahi=0, Alo=PLANE, Bhi=2P, Blo=3P.
// ---------------------------------------------------------------------------
__device__ __forceinline__ void mma_chunk(uint32_t sb, const uint32_t* aoff,
                                          const uint32_t* boff, float (*acc)[4][4]) {
    uint32_t af[4][4], bh[2][4], bl[2][4];
#pragma unroll
    for (int ks = 0; ks < 4; ks++) {
        uint32_t kb = ks * 32;
#pragma unroll
        for (int wm = 0; wm < 4; wm++) ldsm4(af[wm], sb + aoff[wm] + kb);
#pragma unroll
        for (int p = 0; p < 2; p++) ldsm4(bh[p], sb + 2 * PLANE + boff[p] + kb);
#pragma unroll
        for (int p = 0; p < 2; p++) ldsm4(bl[p], sb + 3 * PLANE + boff[p] + kb);
#pragma unroll
        for (int wm = 0; wm < 4; wm++)
#pragma unroll
            for (int wn = 0; wn < 4; wn++) {
                mma_bf16(acc[wm][wn], af[wm], bh[wn >> 1][(wn & 1) * 2], bh[wn >> 1][(wn & 1) * 2 + 1]);
                mma_bf16(acc[wm][wn], af[wm], bl[wn >> 1][(wn & 1) * 2], bl[wn >> 1][(wn & 1) * 2 + 1]);
            }
#pragma unroll
        for (int wm = 0; wm < 4; wm++) ldsm4(af[wm], sb + PLANE + aoff[wm] + kb);
#pragma unroll
        for (int wm = 0; wm < 4; wm++)
#pragma unroll
            for (int wn = 0; wn < 4; wn++)
                mma_bf16(acc[wm][wn], af[wm], bh[wn >> 1][(wn & 1) * 2], bh[wn >> 1][(wn & 1) * 2 + 1]);
    }
}

// Per-lane ldmatrix offsets (byte offsets within a plane)
__device__ __forceinline__ void frag_offsets(int lane, int warp_m, int warp_n,
                                             uint32_t* aoff, uint32_t* boff) {
    int rowA = lane & 15;
    int kA = (lane >> 4) * 8;
#pragma unroll
    for (int wm = 0; wm < 4; wm++)
        aoff[wm] = (uint32_t)((warp_m * 64 + wm * 16 + rowA) * (PADK * 2) + kA * 2);
    int rowB = (lane & 7) + ((lane >> 4) << 3);
    int kB = (lane & 8) ? 8 : 0;
#pragma unroll
    for (int p = 0; p < 2; p++)
        boff[p] = (uint32_t)((warp_n * 32 + p * 16 + rowB) * (PADK * 2) + kB * 2);
}

// ---------------------------------------------------------------------------
// Projection: C[M,512] = A[M,1024]*W[512,1024]^T + bias -> bf16 hi/lo.
// transpose=1 (V): writes WVT[b][n][s] via smem transpose.
// ---------------------------------------------------------------------------
__global__ __launch_bounds__(256, 2)
void proj_kernel(const float* __restrict__ A, const float* __restrict__ W,
                 const float* __restrict__ bias,
                 __nv_bfloat16* __restrict__ Chi, __nv_bfloat16* __restrict__ Clo,
                 int transpose)
{
    extern __shared__ char smem[];
    uint32_t sb = smem_u32(smem);
    const int tid = threadIdx.x, lane = tid & 31, wid = tid >> 5;
    const int warp_m = wid & 1, warp_n = wid >> 1;
    const int m0 = blockIdx.y * BM, n0 = blockIdx.x * BN;

    float acc[4][4][4];
#pragma unroll
    for (int i = 0; i < 4; i++)
#pragma unroll
        for (int j = 0; j < 4; j++)
#pragma unroll
            for (int r = 0; r < 4; r++) acc[i][j][r] = 0.f;

    uint32_t aoff[4], boff[2];
    frag_offsets(lane, warp_m, warp_n, aoff, boff);

    const int lrow = tid >> 1, lhalf = (tid & 1) * 32;
    char* dA = smem + lrow * (PADK * 2) + lhalf * 2;
    char* dB = dA + 2 * PLANE;

    for (int ch = 0; ch < DD / BKC; ch++) {
        int k0 = ch * BKC;
        load_split32(A + (size_t)(m0 + lrow) * DD + k0 + lhalf, dA, dA + PLANE);
        load_split32(W + (size_t)(n0 + lrow) * DD + k0 + lhalf, dB, dB + PLANE);
        __syncthreads();
        mma_chunk(sb, aoff, boff, acc);
        __syncthreads();
    }

    if (!transpose) {
#pragma unroll
        for (int wn = 0; wn < 4; wn++) {
            int n = n0 + warp_n * 32 + wn * 8 + (lane & 3) * 2;
            float b0 = bias[n], b1 = bias[n + 1];
#pragma unroll
            for (int wm = 0; wm < 4; wm++)
#pragma unroll
                for (int h = 0; h < 2; h++) {
                    int m = m0 + warp_m * 64 + wm * 16 + (lane >> 2) + h * 8;
                    uint32_t hv, lv;
                    split2(acc[wm][wn][h * 2] + b0, acc[wm][wn][h * 2 + 1] + b1, hv, lv);
                    *reinterpret_cast<uint32_t*>(Chi + (size_t)m * AA + n) = hv;
                    *reinterpret_cast<uint32_t*>(Clo + (size_t)m * AA + n) = lv;
                }
        }
    } else {
        // Transpose through smem: T[n][m] planes (stride 136 bf16 = 272B)
        char* T = smem;
#pragma unroll
        for (int wn = 0; wn < 4; wn++) {
            int ln = warp_n * 32 + wn * 8 + (lane & 3) * 2;
            float b0 = bias[n0 + ln], b1 = bias[n0 + ln + 1];
#pragma unroll
            for (int wm = 0; wm < 4; wm++)
#pragma unroll
                for (int h = 0; h < 2; h++) {
                    int lm = warp_m * 64 + wm * 16 + (lane >> 2) + h * 8;
                    float v0 = acc[wm][wn][h * 2] + b0;
                    float v1 = acc[wm][wn][h * 2 + 1] + b1;
                    __nv_bfloat16 h0 = __float2bfloat16_rn(v0);
                    __nv_bfloat16 l0 = __float2bfloat16_rn(v0 - __bfloat162float(h0));
                    __nv_bfloat16 h1 = __float2bfloat16_rn(v1);
                    __nv_bfloat16 l1 = __float2bfloat16_rn(v1 - __bfloat162float(h1));
                    *reinterpret_cast<__nv_bfloat16*>(T + ln * 272 + lm * 2) = h0;
                    *reinterpret_cast<__nv_bfloat16*>(T + (ln + 1) * 272 + lm * 2) = h1;
                    *reinterpret_cast<__nv_bfloat16*>(T + 34816 + ln * 272 + lm * 2) = l0;
                    *reinterpret_cast<__nv_bfloat16*>(T + 34816 + (ln + 1) * 272 + lm * 2) = l1;
                }
        }
        __syncthreads();
        int v = tid >> 1, hs = (tid & 1) * 64;
        size_t b = (size_t)(m0 >> 11);
        int s0 = m0 & (SS - 1);
        __nv_bfloat16* dh = Chi + (b * DVV + n0 + v) * SS + s0 + hs;
        __nv_bfloat16* dl = Clo + (b * DVV + n0 + v) * SS + s0 + hs;
#pragma unroll
        for (int g = 0; g < 8; g++) {
            *reinterpret_cast<uint4*>(dh + g * 8) =
                *reinterpret_cast<uint4*>(T + v * 272 + (hs + g * 8) * 2);
            *reinterpret_cast<uint4*>(dl + g * 8) =
                *reinterpret_cast<uint4*>(T + 34816 + v * 272 + (hs + g * 8) * 2);
        }
    }
}

// ---------------------------------------------------------------------------
// Scores (pre-transposed): attn[b][k][q] = scale*Kp[k]·Qp[q] - 1e9*mask[b][q][k]
// ---------------------------------------------------------------------------
__global__ __launch_bounds__(256, 2)
void scores_kernel(const __nv_bfloat16* __restrict__ KpHi, const __nv_bfloat16* __restrict__ KpLo,
                   const __nv_bfloat16* __restrict__ QpHi, const __nv_bfloat16* __restrict__ QpLo,
                   const int* __restrict__ mask, float* __restrict__ attn)
{
    extern __shared__ char smem[];
    uint32_t sb = smem_u32(smem);
    const int tid = threadIdx.x, lane = tid & 31, wid = tid >> 5;
    const int warp_m = wid & 1, warp_n = wid >> 1;
    const int m0 = blockIdx.y * BM, n0 = blockIdx.x * BN, b = blockIdx.z;

    float acc[4][4][4];
#pragma unroll
    for (int i = 0; i < 4; i++)
#pragma unroll
        for (int j = 0; j < 4; j++)
#pragma unroll
            for (int r = 0; r < 4; r++) acc[i][j][r] = 0.f;

    uint32_t aoff[4], boff[2];
    frag_offsets(lane, warp_m, warp_n, aoff, boff);

    const int lrow = tid >> 1, lhalf = (tid & 1) * 32;
    char* dA = smem + lrow * (PADK * 2) + lhalf * 2;
    char* dB = dA + 2 * PLANE;
    const size_t base = (size_t)b * SS * AA;

    for (int ch = 0; ch < AA / BKC; ch++) {
        int k0 = ch * BKC;
        size_t ra = base + (size_t)(m0 + lrow) * AA + k0 + lhalf;
        size_t rb = base + (size_t)(n0 + lrow) * AA + k0 + lhalf;
        load_copy32(KpHi + ra, KpLo + ra, dA, dA + PLANE);
        load_copy32(QpHi + rb, QpLo + rb, dB, dB + PLANE);
        __syncthreads();
        mma_chunk(sb, aoff, boff, acc);
        __syncthreads();
    }

    const float scale = 0.04419417382415922f;   // 1/sqrt(512)
    const int* mk = mask + (size_t)b * SS * SS;
    float* ab = attn + (size_t)b * SS * SS;
#pragma unroll
    for (int wm = 0; wm < 4; wm++)
#pragma unroll
        for (int h = 0; h < 2; h++) {
            int k = m0 + warp_m * 64 + wm * 16 + (lane >> 2) + h * 8;
#pragma unroll
            for (int wn = 0; wn < 4; wn++) {
                int q = n0 + warp_n * 32 + wn * 8 + (lane & 3) * 2;
                float m0v = (float)mk[(size_t)q * SS + k];
                float m1v = (float)mk[(size_t)(q + 1) * SS + k];
                float2 v = make_float2(acc[wm][wn][h * 2] * scale - 1e9f * m0v,
                                       acc[wm][wn][h * 2 + 1] * scale - 1e9f * m1v);
                *reinterpret_cast<float2*>(ab + (size_t)k * SS + q) = v;
            }
        }
}

// ---------------------------------------------------------------------------
// Output: out[b][k][v] = sum_q attn[b][k][q] * WVT[b][v][q]
// ---------------------------------------------------------------------------
__global__ __launch_bounds__(256, 2)
void out_kernel(const float* __restrict__ attn,
                const __nv_bfloat16* __restrict__ WVTHi, const __nv_bfloat16* __restrict__ WVTLo,
                float* __restrict__ out)
{
    extern __shared__ char smem[];
    uint32_t sb = smem_u32(smem);
    const int tid = threadIdx.x, lane = tid & 31, wid = tid >> 5;
    const int warp_m = wid & 1, warp_n = wid >> 1;
    const int m0 = blockIdx.y * BM, n0 = blockIdx.x * BN, b = blockIdx.z;

    float acc[4][4][4];
#pragma unroll
    for (int i = 0; i < 4; i++)
#pragma unroll
        for (int j = 0; j < 4; j++)
#pragma unroll
            for (int r = 0; r < 4; r++) acc[i][j][r] = 0.f;

    uint32_t aoff[4], boff[2];
    frag_offsets(lane, warp_m, warp_n, aoff, boff);

    const int lrow = tid >> 1, lhalf = (tid & 1) * 32;
    char* dA = smem + lrow * (PADK * 2) + lhalf * 2;
    char* dB = dA + 2 * PLANE;
    const float* Ab = attn + (size_t)b * SS * SS;

    for (int ch = 0; ch < SS / BKC; ch++) {
        int k0 = ch * BKC;
        load_split32(Ab + (size_t)(m0 + lrow) * SS + k0 + lhalf, dA, dA + PLANE);
        size_t rb = ((size_t)b * DVV + n0 + lrow) * SS + k0 + lhalf;
        load_copy32(WVTHi + rb, WVTLo + rb, dB, dB + PLANE);
        __syncthreads();
        mma_chunk(sb, aoff, boff, acc);
        __syncthreads();
    }

    float* ob = out + (size_t)b * SS * DVV;
#pragma unroll
    for (int wm = 0; wm < 4; wm++)
#pragma unroll
        for (int h = 0; h < 2; h++) {
            int m = m0 + warp_m * 64 + wm * 16 + (lane >> 2) + h * 8;
#pragma unroll
            for (int wn = 0; wn < 4; wn++) {
                int n = n0 + warp_n * 32 + wn * 8 + (lane & 3) * 2;
                *reinterpret_cast<float2*>(ob + (size_t)m * DVV + n) =
                    make_float2(acc[wm][wn][h * 2], acc[wm][wn][h * 2 + 1]);
            }
        }
}

// ---------------------------------------------------------------------------
// In-place row softmax, rows of length SS. 256 threads per row.
// ---------------------------------------------------------------------------
__global__ void softmax_rows(float* __restrict__ p)
{
    __shared__ float red[33];
    float* x = p + (size_t)blockIdx.x * SS;
    int tid = threadIdx.x;
    float v[8];
    float mx = -1e30f;
#pragma unroll
    for (int i = 0; i < 8; i++) { v[i] = x[tid + i * 256]; mx = fmaxf(mx, v[i]); }
#pragma unroll
    for (int o = 16; o > 0; o >>= 1) mx = fmaxf(mx, __shfl_xor_sync(0xffffffffu, mx, o));
    if ((tid & 31) == 0) red[tid >> 5] = mx;
    __syncthreads();
    if (tid < 32) {
        float m = (tid < 8) ? red[tid] : -1e30f;
#pragma unroll
        for (int o = 4; o > 0; o >>= 1) m = fmaxf(m, __shfl_xor_sync(0xffffffffu, m, o));
        if (tid == 0) red[32] = m;
    }
    __syncthreads();
    mx = red[32];
    float s = 0.f;
#pragma unroll
    for (int i = 0; i < 8; i++) { v[i] = __expf(v[i] - mx); s += v[i]; }
#pragma unroll
    for (int o = 16; o > 0; o >>= 1) s += __shfl_xor_sync(0xffffffffu, s, o);
    if ((tid & 31) == 0) red[tid >> 5] = s;
    __syncthreads();
    if (tid < 32) {
        float m = (tid < 8) ? red[tid] : 0.f;
#pragma unroll
        for (int o = 4; o > 0; o >>= 1) m += __shfl_xor_sync(0xffffffffu, m, o);
        if (tid == 0) red[32] = m;
    }
    __syncthreads();
    float inv = 1.0f / red[32];
#pragma unroll
    for (int i = 0; i < 8; i++) x[tid + i * 256] = v[i] * inv;
}

// ---------------------------------------------------------------------------
extern "C" void kernel_launch(void* const* d_in, const int* in_sizes, int n_in,
                              void* d_out, int out_size)
{
    const float* Q    = (const float*)d_in[0];
    const float* K    = (const float*)d_in[1];
    const float* V    = (const float*)d_in[2];
    const int*   mask = (const int*)  d_in[3];
    const float* Wq   = (const float*)d_in[4];
    const float* bq   = (const float*)d_in[5];
    const float* Wk   = (const float*)d_in[6];
    const float* bk   = (const float*)d_in[7];
    const float* Wv   = (const float*)d_in[8];
    const float* bv   = (const float*)d_in[9];

    float* out  = (float*)d_out;                   // selfOutput [B,S,Dv]
    float* attn = out + (size_t)NB * SS * DVV;     // attn       [B,S,S]

    static __nv_bfloat16 *pQpHi, *pQpLo, *pKpHi, *pKpLo, *pWVTHi, *pWVTLo;
    static bool inited = false;
    if (!inited) {
        cudaGetSymbolAddress((void**)&pQpHi, g_QpHi);
        cudaGetSymbolAddress((void**)&pQpLo, g_QpLo);
        cudaGetSymbolAddress((void**)&pKpHi, g_KpHi);
        cudaGetSymbolAddress((void**)&pKpLo, g_KpLo);
        cudaGetSymbolAddress((void**)&pWVTHi, g_WVTHi);
        cudaGetSymbolAddress((void**)&pWVTLo, g_WVTLo);
        cudaFuncSetAttribute(proj_kernel,   cudaFuncAttributeMaxDynamicSharedMemorySize, SMEM_GEMM);
        cudaFuncSetAttribute(scores_kernel, cudaFuncAttributeMaxDynamicSharedMemorySize, SMEM_GEMM);
        cudaFuncSetAttribute(out_kernel,    cudaFuncAttributeMaxDynamicSharedMemorySize, SMEM_GEMM);
        inited = true;
    }

    dim3 blk(256);
    // Projections: M = B*S = 16384 rows, N = 512, K = 1024
    proj_kernel<<<dim3(4, 128), blk, SMEM_GEMM>>>(Q, Wq, bq, pQpHi, pQpLo, 0);
    proj_kernel<<<dim3(4, 128), blk, SMEM_GEMM>>>(K, Wk, bk, pKpHi, pKpLo, 0);
    proj_kernel<<<dim3(4, 128), blk, SMEM_GEMM>>>(V, Wv, bv, pWVTHi, pWVTLo, 1);
    // Masked, pre-transposed scores -> attn slot (K = 512)
    scores_kernel<<<dim3(16, 16, NB), blk, SMEM_GEMM>>>(pKpHi, pKpLo, pQpHi, pQpLo, mask, attn);
    // Row softmax in place
    softmax_rows<<<NB * SS, 256>>>(attn);
    // selfOutput = attn @ WV   (K = 2048)
    out_kernel<<<dim3(4, 16, NB), blk, SMEM_GEMM>>>(attn, pWVTHi, pWVTLo, out);
}

// round 4
// speedup vs baseline: 2.3570x; 1.2195x over previous
#include <cuda_runtime.h>
#include <cuda_bf16.h>
#include <cstdint>

#define NB 8
#define SS 2048
#define DD 1024
#define AA 512
#define DVV 512

// GEMM tiling: 128x128 CTA tile, BK=32, 2-stage cp.async pipeline
#define BM 128
#define BN 128
#define BKC 32
#define ROWB 80                       // bytes per smem row (32 bf16 + 8 pad)
#define PLANE32 (128 * ROWB)          // 10240 B per operand plane
#define STAGE (4 * PLANE32)           // 40960 B per stage
#define SMEM_PIPE (2 * STAGE)         // 81920 B

// ---------------------------------------------------------------------------
// Scratch (__device__ globals; allocation-free rule)
// ---------------------------------------------------------------------------
__device__ __nv_bfloat16 g_QbHi[(size_t)NB * SS * DD];
__device__ __nv_bfloat16 g_QbLo[(size_t)NB * SS * DD];
__device__ __nv_bfloat16 g_KbHi[(size_t)NB * SS * DD];
__device__ __nv_bfloat16 g_KbLo[(size_t)NB * SS * DD];
__device__ __nv_bfloat16 g_VbHi[(size_t)NB * SS * DD];
__device__ __nv_bfloat16 g_VbLo[(size_t)NB * SS * DD];
__device__ __nv_bfloat16 g_WqHi[(size_t)AA * DD];
__device__ __nv_bfloat16 g_WqLo[(size_t)AA * DD];
__device__ __nv_bfloat16 g_WkHi[(size_t)AA * DD];
__device__ __nv_bfloat16 g_WkLo[(size_t)AA * DD];
__device__ __nv_bfloat16 g_WvHi[(size_t)DVV * DD];
__device__ __nv_bfloat16 g_WvLo[(size_t)DVV * DD];
__device__ __nv_bfloat16 g_QpHi[(size_t)NB * SS * AA];
__device__ __nv_bfloat16 g_QpLo[(size_t)NB * SS * AA];
__device__ __nv_bfloat16 g_KpHi[(size_t)NB * SS * AA];
__device__ __nv_bfloat16 g_KpLo[(size_t)NB * SS * AA];
__device__ __nv_bfloat16 g_WVTHi[(size_t)NB * DVV * SS];   // [b][v][s]
__device__ __nv_bfloat16 g_WVTLo[(size_t)NB * DVV * SS];
__device__ __nv_bfloat16 g_AtHi[(size_t)NB * SS * SS];     // attn hi/lo (softmax output)
__device__ __nv_bfloat16 g_AtLo[(size_t)NB * SS * SS];
__device__ __nv_bfloat16 g_MkT[(size_t)NB * SS * SS];      // -1e9*mask, transposed [b][k][q]

// ---------------------------------------------------------------------------
// Helpers
// ---------------------------------------------------------------------------
__device__ __forceinline__ uint32_t smem_u32(const void* p) {
    uint32_t a;
    asm("{ .reg .u64 t; cvta.to.shared.u64 t, %1; cvt.u32.u64 %0, t; }" : "=r"(a) : "l"(p));
    return a;
}
__device__ __forceinline__ void cp16(uint32_t dst, const void* src) {
    asm volatile("cp.async.cg.shared.global [%0], [%1], 16;" :: "r"(dst), "l"(src));
}
#define CP_COMMIT() asm volatile("cp.async.commit_group;" ::: "memory")
#define CP_WAIT0()  asm volatile("cp.async.wait_group 0;" ::: "memory")

__device__ __forceinline__ void ldsm4(uint32_t (&r)[4], uint32_t addr) {
    asm volatile("ldmatrix.sync.aligned.m8n8.x4.shared.b16 {%0,%1,%2,%3}, [%4];"
        : "=r"(r[0]), "=r"(r[1]), "=r"(r[2]), "=r"(r[3]) : "r"(addr));
}
__device__ __forceinline__ void mma_bf16(float* d, const uint32_t* a, uint32_t b0, uint32_t b1) {
    asm volatile("mma.sync.aligned.m16n8k16.row.col.f32.bf16.bf16.f32 "
        "{%0,%1,%2,%3}, {%4,%5,%6,%7}, {%8,%9}, {%0,%1,%2,%3};"
        : "+f"(d[0]), "+f"(d[1]), "+f"(d[2]), "+f"(d[3])
        : "r"(a[0]), "r"(a[1]), "r"(a[2]), "r"(a[3]), "r"(b0), "r"(b1));
}
__device__ __forceinline__ void split2(float a, float b, uint32_t& hi, uint32_t& lo) {
    __nv_bfloat16 ah = __float2bfloat16_rn(a);
    __nv_bfloat16 bh = __float2bfloat16_rn(b);
    __nv_bfloat16 al = __float2bfloat16_rn(a - __bfloat162float(ah));
    __nv_bfloat16 bl = __float2bfloat16_rn(b - __bfloat162float(bh));
    hi = (uint32_t)__bfloat16_as_ushort(ah) | ((uint32_t)__bfloat16_as_ushort(bh) << 16);
    lo = (uint32_t)__bfloat16_as_ushort(al) | ((uint32_t)__bfloat16_as_ushort(bl) << 16);
}

// Per-lane ldmatrix offsets within a stage (plane-relative, stride ROWB)
__device__ __forceinline__ void frag_offsets(int lane, int warp_m, int warp_n,
                                             uint32_t* aoff, uint32_t* boff) {
    int rowA = lane & 15;
    int kA = (lane >> 4) * 8;
#pragma unroll
    for (int wm = 0; wm < 4; wm++)
        aoff[wm] = (uint32_t)((warp_m * 64 + wm * 16 + rowA) * ROWB + kA * 2);
    int rowB = (lane & 7) + ((lane >> 4) << 3);
    int kB = (lane & 8) ? 8 : 0;
#pragma unroll
    for (int p = 0; p < 2; p++)
        boff[p] = (uint32_t)((warp_n * 32 + p * 16 + rowB) * ROWB + kB * 2);
}

// Issue cp.async for one BK=32 chunk into the given stage base
__device__ __forceinline__ void issue_cp(uint32_t sbase,
    const __nv_bfloat16* __restrict__ Ahi, const __nv_bfloat16* __restrict__ Alo, int lda,
    const __nv_bfloat16* __restrict__ Bhi, const __nv_bfloat16* __restrict__ Blo, int ldb,
    int k0, int tid)
{
    const int lrow = tid >> 1;
    const int koff = k0 + (tid & 1) * 16;
    uint32_t d = sbase + (uint32_t)(lrow * ROWB + (tid & 1) * 32);
    const __nv_bfloat16* a0 = Ahi + (size_t)lrow * lda + koff;
    const __nv_bfloat16* a1 = Alo + (size_t)lrow * lda + koff;
    const __nv_bfloat16* b0 = Bhi + (size_t)lrow * ldb + koff;
    const __nv_bfloat16* b1 = Blo + (size_t)lrow * ldb + koff;
    cp16(d, a0);                    cp16(d + 16, a0 + 8);
    cp16(d + PLANE32, a1);          cp16(d + PLANE32 + 16, a1 + 8);
    cp16(d + 2 * PLANE32, b0);      cp16(d + 2 * PLANE32 + 16, b0 + 8);
    cp16(d + 3 * PLANE32, b1);      cp16(d + 3 * PLANE32 + 16, b1 + 8);
}

// One BK=32 chunk of bf16x3 MMA
__device__ __forceinline__ void mma_chunk32(uint32_t sb, const uint32_t* aoff,
                                            const uint32_t* boff, float (*acc)[4][4]) {
#pragma unroll
    for (int ks = 0; ks < 2; ks++) {
        uint32_t kb = ks * 32;
        uint32_t af[4][4], bh[2][4], bl[2][4];
#pragma unroll
        for (int wm = 0; wm < 4; wm++) ldsm4(af[wm], sb + aoff[wm] + kb);
#pragma unroll
        for (int p = 0; p < 2; p++) ldsm4(bh[p], sb + 2 * PLANE32 + boff[p] + kb);
#pragma unroll
        for (int p = 0; p < 2; p++) ldsm4(bl[p], sb + 3 * PLANE32 + boff[p] + kb);
#pragma unroll
        for (int wm = 0; wm < 4; wm++)
#pragma unroll
            for (int wn = 0; wn < 4; wn++) {
                mma_bf16(acc[wm][wn], af[wm], bh[wn >> 1][(wn & 1) * 2], bh[wn >> 1][(wn & 1) * 2 + 1]);
                mma_bf16(acc[wm][wn], af[wm], bl[wn >> 1][(wn & 1) * 2], bl[wn >> 1][(wn & 1) * 2 + 1]);
            }
#pragma unroll
        for (int wm = 0; wm < 4; wm++) ldsm4(af[wm], sb + PLANE32 + aoff[wm] + kb);
#pragma unroll
        for (int wm = 0; wm < 4; wm++)
#pragma unroll
            for (int wn = 0; wn < 4; wn++)
                mma_bf16(acc[wm][wn], af[wm], bh[wn >> 1][(wn & 1) * 2], bh[wn >> 1][(wn & 1) * 2 + 1]);
    }
}

// Pipelined all-bf16 GEMM core (acc += A * B^T over K)
__device__ __forceinline__ void gemm_core(uint32_t sb,
    const __nv_bfloat16* Ahi, const __nv_bfloat16* Alo, int lda,
    const __nv_bfloat16* Bhi, const __nv_bfloat16* Blo, int ldb,
    int K, int tid, const uint32_t* aoff, const uint32_t* boff, float (*acc)[4][4])
{
    const int nch = K / BKC;
    issue_cp(sb, Ahi, Alo, lda, Bhi, Blo, ldb, 0, tid);
    CP_COMMIT();
    for (int ch = 0; ch < nch; ch++) {
        uint32_t cur = (uint32_t)(ch & 1) * STAGE;
        CP_WAIT0();
        __syncthreads();
        if (ch + 1 < nch) {
            issue_cp(sb + (STAGE - cur), Ahi, Alo, lda, Bhi, Blo, ldb, (ch + 1) * BKC, tid);
            CP_COMMIT();
        }
        mma_chunk32(sb + cur, aoff, boff, acc);
    }
    __syncthreads();
}

// ---------------------------------------------------------------------------
// Elementwise fp32 -> bf16 hi/lo split
// ---------------------------------------------------------------------------
__global__ void split_kernel(const float* __restrict__ in,
                             __nv_bfloat16* __restrict__ hi,
                             __nv_bfloat16* __restrict__ lo, int n4)
{
    int i = blockIdx.x * blockDim.x + threadIdx.x;
    if (i < n4) {
        float4 v = reinterpret_cast<const float4*>(in)[i];
        uint32_t h0, l0, h1, l1;
        split2(v.x, v.y, h0, l0);
        split2(v.z, v.w, h1, l1);
        reinterpret_cast<uint2*>(hi)[i] = make_uint2(h0, h1);
        reinterpret_cast<uint2*>(lo)[i] = make_uint2(l0, l1);
    }
}

// ---------------------------------------------------------------------------
// Mask transpose + prescale: mT[b][k][q] = bf16(-1e9 * mask[b][q][k])
// ---------------------------------------------------------------------------
__global__ __launch_bounds__(256)
void maskT_kernel(const int* __restrict__ mask, __nv_bfloat16* __restrict__ mT)
{
    __shared__ float t[32][33];
    const int b = blockIdx.z;
    const int q0 = blockIdx.y * 32, k0 = blockIdx.x * 32;
    const int* mb = mask + (size_t)b * SS * SS;
    __nv_bfloat16* ob = mT + (size_t)b * SS * SS;
#pragma unroll
    for (int i = 0; i < 4; i++) {
        int q = q0 + threadIdx.y + i * 8;
        t[threadIdx.y + i * 8][threadIdx.x] =
            -1e9f * (float)mb[(size_t)q * SS + k0 + threadIdx.x];
    }
    __syncthreads();
#pragma unroll
    for (int i = 0; i < 4; i++) {
        int k = k0 + threadIdx.y + i * 8;
        ob[(size_t)k * SS + q0 + threadIdx.x] =
            __float2bfloat16_rn(t[threadIdx.x][threadIdx.y + i * 8]);
    }
}

// ---------------------------------------------------------------------------
// Projection: C[M,512] = A[M,1024]*W[512,1024]^T + bias -> bf16 hi/lo
// transpose=1 (V): writes WVT[b][n][s] via smem transpose.
// ---------------------------------------------------------------------------
__global__ __launch_bounds__(256, 2)
void proj_kernel(const __nv_bfloat16* __restrict__ Ahi, const __nv_bfloat16* __restrict__ Alo,
                 const __nv_bfloat16* __restrict__ Whi, const __nv_bfloat16* __restrict__ Wlo,
                 const float* __restrict__ bias,
                 __nv_bfloat16* __restrict__ Chi, __nv_bfloat16* __restrict__ Clo,
                 int transpose)
{
    extern __shared__ char smem[];
    uint32_t sb = smem_u32(smem);
    const int tid = threadIdx.x, lane = tid & 31, wid = tid >> 5;
    const int warp_m = wid & 1, warp_n = wid >> 1;
    const int m0 = blockIdx.y * BM, n0 = blockIdx.x * BN;

    float acc[4][4][4];
#pragma unroll
    for (int i = 0; i < 4; i++)
#pragma unroll
        for (int j = 0; j < 4; j++)
#pragma unroll
            for (int r = 0; r < 4; r++) acc[i][j][r] = 0.f;

    uint32_t aoff[4], boff[2];
    frag_offsets(lane, warp_m, warp_n, aoff, boff);

    gemm_core(sb, Ahi + (size_t)m0 * DD, Alo + (size_t)m0 * DD, DD,
              Whi + (size_t)n0 * DD, Wlo + (size_t)n0 * DD, DD,
              DD, tid, aoff, boff, acc);

    if (!transpose) {
#pragma unroll
        for (int wn = 0; wn < 4; wn++) {
            int n = n0 + warp_n * 32 + wn * 8 + (lane & 3) * 2;
            float b0 = bias[n], b1 = bias[n + 1];
#pragma unroll
            for (int wm = 0; wm < 4; wm++)
#pragma unroll
                for (int h = 0; h < 2; h++) {
                    int m = m0 + warp_m * 64 + wm * 16 + (lane >> 2) + h * 8;
                    uint32_t hv, lv;
                    split2(acc[wm][wn][h * 2] + b0, acc[wm][wn][h * 2 + 1] + b1, hv, lv);
                    *reinterpret_cast<uint32_t*>(Chi + (size_t)m * AA + n) = hv;
                    *reinterpret_cast<uint32_t*>(Clo + (size_t)m * AA + n) = lv;
                }
        }
    } else {
        char* T = smem;   // stride 272B rows; hi plane at 0, lo plane at 34816
#pragma unroll
        for (int wn = 0; wn < 4; wn++) {
            int ln = warp_n * 32 + wn * 8 + (lane & 3) * 2;
            float b0 = bias[n0 + ln], b1 = bias[n0 + ln + 1];
#pragma unroll
            for (int wm = 0; wm < 4; wm++)
#pragma unroll
                for (int h = 0; h < 2; h++) {
                    int lm = warp_m * 64 + wm * 16 + (lane >> 2) + h * 8;
                    float v0 = acc[wm][wn][h * 2] + b0;
                    float v1 = acc[wm][wn][h * 2 + 1] + b1;
                    __nv_bfloat16 h0 = __float2bfloat16_rn(v0);
                    __nv_bfloat16 l0 = __float2bfloat16_rn(v0 - __bfloat162float(h0));
                    __nv_bfloat16 h1 = __float2bfloat16_rn(v1);
                    __nv_bfloat16 l1 = __float2bfloat16_rn(v1 - __bfloat162float(h1));
                    *reinterpret_cast<__nv_bfloat16*>(T + ln * 272 + lm * 2) = h0;
                    *reinterpret_cast<__nv_bfloat16*>(T + (ln + 1) * 272 + lm * 2) = h1;
                    *reinterpret_cast<__nv_bfloat16*>(T + 34816 + ln * 272 + lm * 2) = l0;
                    *reinterpret_cast<__nv_bfloat16*>(T + 34816 + (ln + 1) * 272 + lm * 2) = l1;
                }
        }
        __syncthreads();
        int v = tid >> 1, hs = (tid & 1) * 64;
        size_t b = (size_t)(m0 >> 11);
        int s0 = m0 & (SS - 1);
        __nv_bfloat16* dh = Chi + (b * DVV + n0 + v) * SS + s0 + hs;
        __nv_bfloat16* dl = Clo + (b * DVV + n0 + v) * SS + s0 + hs;
#pragma unroll
        for (int g = 0; g < 8; g++) {
            *reinterpret_cast<uint4*>(dh + g * 8) =
                *reinterpret_cast<uint4*>(T + v * 272 + (hs + g * 8) * 2);
            *reinterpret_cast<uint4*>(dl + g * 8) =
                *reinterpret_cast<uint4*>(T + 34816 + v * 272 + (hs + g * 8) * 2);
        }
    }
}

// ---------------------------------------------------------------------------
// Scores (pre-transposed): attn[b][k][q] = scale*Kp[k]·Qp[q] + mT[b][k][q]
// ---------------------------------------------------------------------------
__global__ __launch_bounds__(256, 2)
void scores_kernel(const __nv_bfloat16* __restrict__ KpHi, const __nv_bfloat16* __restrict__ KpLo,
                   const __nv_bfloat16* __restrict__ QpHi, const __nv_bfloat16* __restrict__ QpLo,
                   const __nv_bfloat16* __restrict__ mT, float* __restrict__ attn)
{
    extern __shared__ char smem[];
    uint32_t sb = smem_u32(smem);
    const int tid = threadIdx.x, lane = tid & 31, wid = tid >> 5;
    const int warp_m = wid & 1, warp_n = wid >> 1;
    const int m0 = blockIdx.y * BM, n0 = blockIdx.x * BN, b = blockIdx.z;

    float acc[4][4][4];
#pragma unroll
    for (int i = 0; i < 4; i++)
#pragma unroll
        for (int j = 0; j < 4; j++)
#pragma unroll
            for (int r = 0; r < 4; r++) acc[i][j][r] = 0.f;

    uint32_t aoff[4], boff[2];
    frag_offsets(lane, warp_m, warp_n, aoff, boff);

    const size_t base = (size_t)b * SS * AA;
    gemm_core(sb, KpHi + base + (size_t)m0 * AA, KpLo + base + (size_t)m0 * AA, AA,
              QpHi + base + (size_t)n0 * AA, QpLo + base + (size_t)n0 * AA, AA,
              AA, tid, aoff, boff, acc);

    const float scale = 0.04419417382415922f;   // 1/sqrt(512)
    const __nv_bfloat16* mb = mT + (size_t)b * SS * SS;
    float* ab = attn + (size_t)b * SS * SS;
#pragma unroll
    for (int wm = 0; wm < 4; wm++)
#pragma unroll
        for (int h = 0; h < 2; h++) {
            int k = m0 + warp_m * 64 + wm * 16 + (lane >> 2) + h * 8;
#pragma unroll
            for (int wn = 0; wn < 4; wn++) {
                int q = n0 + warp_n * 32 + wn * 8 + (lane & 3) * 2;
                uint32_t mu = *reinterpret_cast<const uint32_t*>(mb + (size_t)k * SS + q);
                float mv0 = __bfloat162float(__ushort_as_bfloat16((unsigned short)(mu & 0xFFFF)));
                float mv1 = __bfloat162float(__ushort_as_bfloat16((unsigned short)(mu >> 16)));
                *reinterpret_cast<float2*>(ab + (size_t)k * SS + q) =
                    make_float2(fmaf(acc[wm][wn][h * 2], scale, mv0),
                                fmaf(acc[wm][wn][h * 2 + 1], scale, mv1));
            }
        }
}

// ---------------------------------------------------------------------------
// Output: out[b][k][v] = sum_q attn[b][k][q] * WVT[b][v][q]
// ---------------------------------------------------------------------------
__global__ __launch_bounds__(256, 2)
void out_kernel(const __nv_bfloat16* __restrict__ AtHi, const __nv_bfloat16* __restrict__ AtLo,
                const __nv_bfloat16* __restrict__ WVTHi, const __nv_bfloat16* __restrict__ WVTLo,
                float* __restrict__ out)
{
    extern __shared__ char smem[];
    uint32_t sb = smem_u32(smem);
    const int tid = threadIdx.x, lane = tid & 31, wid = tid >> 5;
    const int warp_m = wid & 1, warp_n = wid >> 1;
    const int m0 = blockIdx.y * BM, n0 = blockIdx.x * BN, b = blockIdx.z;

    float acc[4][4][4];
#pragma unroll
    for (int i = 0; i < 4; i++)
#pragma unroll
        for (int j = 0; j < 4; j++)
#pragma unroll
            for (int r = 0; r < 4; r++) acc[i][j][r] = 0.f;

    uint32_t aoff[4], boff[2];
    frag_offsets(lane, warp_m, warp_n, aoff, boff);

    const size_t abase = (size_t)b * SS * SS;
    const size_t bbase = (size_t)b * DVV * SS;
    gemm_core(sb, AtHi + abase + (size_t)m0 * SS, AtLo + abase + (size_t)m0 * SS, SS,
              WVTHi + bbase + (size_t)n0 * SS, WVTLo + bbase + (size_t)n0 * SS, SS,
              SS, tid, aoff, boff, acc);

    float* ob = out + (size_t)b * SS * DVV;
#pragma unroll
    for (int wm = 0; wm < 4; wm++)
#pragma unroll
        for (int h = 0; h < 2; h++) {
            int m = m0 + warp_m * 64 + wm * 16 + (lane >> 2) + h * 8;
#pragma unroll
            for (int wn = 0; wn < 4; wn++) {
                int n = n0 + warp_n * 32 + wn * 8 + (lane & 3) * 2;
                *reinterpret_cast<float2*>(ob + (size_t)m * DVV + n) =
                    make_float2(acc[wm][wn][h * 2], acc[wm][wn][h * 2 + 1]);
            }
        }
}

// ---------------------------------------------------------------------------
// In-place row softmax (fp32) + bf16 hi/lo split write for the out GEMM.
// ---------------------------------------------------------------------------
__global__ void softmax_rows(float* __restrict__ p,
                             __nv_bfloat16* __restrict__ hi,
                             __nv_bfloat16* __restrict__ lo)
{
    __shared__ float red[33];
    size_t rb = (size_t)blockIdx.x * SS;
    float* x = p + rb;
    int tid = threadIdx.x;
    float v[8];
    float mx = -1e30f;
#pragma unroll
    for (int i = 0; i < 8; i++) { v[i] = x[tid + i * 256]; mx = fmaxf(mx, v[i]); }
#pragma unroll
    for (int o = 16; o > 0; o >>= 1) mx = fmaxf(mx, __shfl_xor_sync(0xffffffffu, mx, o));
    if ((tid & 31) == 0) red[tid >> 5] = mx;
    __syncthreads();
    if (tid < 32) {
        float m = (tid < 8) ? red[tid] : -1e30f;
#pragma unroll
        for (int o = 4; o > 0; o >>= 1) m = fmaxf(m, __shfl_xor_sync(0xffffffffu, m, o));
        if (tid == 0) red[32] = m;
    }
    __syncthreads();
    mx = red[32];
    float s = 0.f;
#pragma unroll
    for (int i = 0; i < 8; i++) { v[i] = __expf(v[i] - mx); s += v[i]; }
#pragma unroll
    for (int o = 16; o > 0; o >>= 1) s += __shfl_xor_sync(0xffffffffu, s, o);
    if ((tid & 31) == 0) red[tid >> 5] = s;
    __syncthreads();
    if (tid < 32) {
        float m = (tid < 8) ? red[tid] : 0.f;
#pragma unroll
        for (int o = 4; o > 0; o >>= 1) m += __shfl_xor_sync(0xffffffffu, m, o);
        if (tid == 0) red[32] = m;
    }
    __syncthreads();
    float inv = 1.0f / red[32];
#pragma unroll
    for (int i = 0; i < 8; i++) {
        int idx = tid + i * 256;
        float val = v[i] * inv;
        x[idx] = val;
        __nv_bfloat16 h = __float2bfloat16_rn(val);
        hi[rb + idx] = h;
        lo[rb + idx] = __float2bfloat16_rn(val - __bfloat162float(h));
    }
}

// ---------------------------------------------------------------------------
extern "C" void kernel_launch(void* const* d_in, const int* in_sizes, int n_in,
                              void* d_out, int out_size)
{
    const float* Q    = (const float*)d_in[0];
    const float* K    = (const float*)d_in[1];
    const float* V    = (const float*)d_in[2];
    const int*   mask = (const int*)  d_in[3];
    const float* Wq   = (const float*)d_in[4];
    const float* bq   = (const float*)d_in[5];
    const float* Wk   = (const float*)d_in[6];
    const float* bk   = (const float*)d_in[7];
    const float* Wv   = (const float*)d_in[8];
    const float* bv   = (const float*)d_in[9];

    float* out  = (float*)d_out;                   // selfOutput [B,S,Dv]
    float* attn = out + (size_t)NB * SS * DVV;     // attn       [B,S,S]

    static __nv_bfloat16 *pQbHi, *pQbLo, *pKbHi, *pKbLo, *pVbHi, *pVbLo;
    static __nv_bfloat16 *pWqHi, *pWqLo, *pWkHi, *pWkLo, *pWvHi, *pWvLo;
    static __nv_bfloat16 *pQpHi, *pQpLo, *pKpHi, *pKpLo, *pWVTHi, *pWVTLo;
    static __nv_bfloat16 *pAtHi, *pAtLo, *pMkT;
    static bool inited = false;
    if (!inited) {
        cudaGetSymbolAddress((void**)&pQbHi, g_QbHi);   cudaGetSymbolAddress((void**)&pQbLo, g_QbLo);
        cudaGetSymbolAddress((void**)&pKbHi, g_KbHi);   cudaGetSymbolAddress((void**)&pKbLo, g_KbLo);
        cudaGetSymbolAddress((void**)&pVbHi, g_VbHi);   cudaGetSymbolAddress((void**)&pVbLo, g_VbLo);
        cudaGetSymbolAddress((void**)&pWqHi, g_WqHi);   cudaGetSymbolAddress((void**)&pWqLo, g_WqLo);
        cudaGetSymbolAddress((void**)&pWkHi, g_WkHi);   cudaGetSymbolAddress((void**)&pWkLo, g_WkLo);
        cudaGetSymbolAddress((void**)&pWvHi, g_WvHi);   cudaGetSymbolAddress((void**)&pWvLo, g_WvLo);
        cudaGetSymbolAddress((void**)&pQpHi, g_QpHi);   cudaGetSymbolAddress((void**)&pQpLo, g_QpLo);
        cudaGetSymbolAddress((void**)&pKpHi, g_KpHi);   cudaGetSymbolAddress((void**)&pKpLo, g_KpLo);
        cudaGetSymbolAddress((void**)&pWVTHi, g_WVTHi); cudaGetSymbolAddress((void**)&pWVTLo, g_WVTLo);
        cudaGetSymbolAddress((void**)&pAtHi, g_AtHi);   cudaGetSymbolAddress((void**)&pAtLo, g_AtLo);
        cudaGetSymbolAddress((void**)&pMkT, g_MkT);
        cudaFuncSetAttribute(proj_kernel,   cudaFuncAttributeMaxDynamicSharedMemorySize, SMEM_PIPE);
        cudaFuncSetAttribute(scores_kernel, cudaFuncAttributeMaxDynamicSharedMemorySize, SMEM_PIPE);
        cudaFuncSetAttribute(out_kernel,    cudaFuncAttributeMaxDynamicSharedMemorySize, SMEM_PIPE);
        inited = true;
    }

    // 1) Pre-split fp32 inputs to bf16 hi/lo
    {
        int n4 = (NB * SS * DD) / 4;
        int g = (n4 + 255) / 256;
        split_kernel<<<g, 256>>>(Q, pQbHi, pQbLo, n4);
        split_kernel<<<g, 256>>>(K, pKbHi, pKbLo, n4);
        split_kernel<<<g, 256>>>(V, pVbHi, pVbLo, n4);
        int w4 = (AA * DD) / 4;
        int gw = (w4 + 255) / 256;
        split_kernel<<<gw, 256>>>(Wq, pWqHi, pWqLo, w4);
        split_kernel<<<gw, 256>>>(Wk, pWkHi, pWkLo, w4);
        split_kernel<<<gw, 256>>>(Wv, pWvHi, pWvLo, w4);
    }
    // 2) Mask transpose + prescale
    maskT_kernel<<<dim3(SS / 32, SS / 32, NB), dim3(32, 8)>>>(mask, pMkT);

    dim3 blk(256);
    // 3) Projections: M = 16384, N = 512, K = 1024
    proj_kernel<<<dim3(4, 128), blk, SMEM_PIPE>>>(pQbHi, pQbLo, pWqHi, pWqLo, bq, pQpHi, pQpLo, 0);
    proj_kernel<<<dim3(4, 128), blk, SMEM_PIPE>>>(pKbHi, pKbLo, pWkHi, pWkLo, bk, pKpHi, pKpLo, 0);
    proj_kernel<<<dim3(4, 128), blk, SMEM_PIPE>>>(pVbHi, pVbLo, pWvHi, pWvLo, bv, pWVTHi, pWVTLo, 1);
    // 4) Masked, pre-transposed scores -> attn (fp32, in d_out)
    scores_kernel<<<dim3(16, 16, NB), blk, SMEM_PIPE>>>(pKpHi, pKpLo, pQpHi, pQpLo, pMkT, attn);
    // 5) Row softmax in place + bf16 hi/lo side-write
    softmax_rows<<<NB * SS, 256>>>(attn, pAtHi, pAtLo);
    // 6) selfOutput = attn @ WV  (K = 2048)
    out_kernel<<<dim3(4, 16, NB), blk, SMEM_PIPE>>>(pAtHi, pAtLo, pWVTHi, pWVTLo, out);
}

// round 5
// speedup vs baseline: 2.5225x; 1.0702x over previous
#include <cuda_runtime.h>
#include <cuda_bf16.h>
#include <cstdint>

#define NB 8
#define SS 2048
#define DD 1024
#define AA 512
#define DVV 512

// GEMM tiling: 128x128 CTA tile, BK=32, 3-stage cp.async pipeline, swizzled smem
#define BM 128
#define BN 128
#define BKC 32
#define ROW64 64                      // bytes per smem row (32 bf16, no pad; XOR swizzle)
#define PLANE (128 * ROW64)           // 8192 B per operand plane
#define STAGE (4 * PLANE)             // 32768 B per stage
#define NSTAGE 3
#define SMEM_PIPE (NSTAGE * STAGE)    // 98304 B

// ---------------------------------------------------------------------------
// Scratch (__device__ globals; allocation-free rule)
// ---------------------------------------------------------------------------
__device__ __nv_bfloat16 g_QbHi[(size_t)NB * SS * DD];
__device__ __nv_bfloat16 g_QbLo[(size_t)NB * SS * DD];
__device__ __nv_bfloat16 g_KbHi[(size_t)NB * SS * DD];
__device__ __nv_bfloat16 g_KbLo[(size_t)NB * SS * DD];
__device__ __nv_bfloat16 g_VbHi[(size_t)NB * SS * DD];
__device__ __nv_bfloat16 g_VbLo[(size_t)NB * SS * DD];
__device__ __nv_bfloat16 g_WqHi[(size_t)AA * DD];
__device__ __nv_bfloat16 g_WqLo[(size_t)AA * DD];
__device__ __nv_bfloat16 g_WkHi[(size_t)AA * DD];
__device__ __nv_bfloat16 g_WkLo[(size_t)AA * DD];
__device__ __nv_bfloat16 g_WvHi[(size_t)DVV * DD];
__device__ __nv_bfloat16 g_WvLo[(size_t)DVV * DD];
__device__ __nv_bfloat16 g_QpHi[(size_t)NB * SS * AA];
__device__ __nv_bfloat16 g_QpLo[(size_t)NB * SS * AA];
__device__ __nv_bfloat16 g_KpHi[(size_t)NB * SS * AA];
__device__ __nv_bfloat16 g_KpLo[(size_t)NB * SS * AA];
__device__ __nv_bfloat16 g_WVTHi[(size_t)NB * DVV * SS];   // [b][v][s]
__device__ __nv_bfloat16 g_WVTLo[(size_t)NB * DVV * SS];
__device__ __nv_bfloat16 g_AtHi[(size_t)NB * SS * SS];
__device__ __nv_bfloat16 g_AtLo[(size_t)NB * SS * SS];
__device__ __nv_bfloat16 g_MkT[(size_t)NB * SS * SS];      // -1e9*mask, transposed [b][k][q]

// ---------------------------------------------------------------------------
// Helpers
// ---------------------------------------------------------------------------
__device__ __forceinline__ uint32_t smem_u32(const void* p) {
    uint32_t a;
    asm("{ .reg .u64 t; cvta.to.shared.u64 t, %1; cvt.u32.u64 %0, t; }" : "=r"(a) : "l"(p));
    return a;
}
__device__ __forceinline__ void cp16(uint32_t dst, const void* src) {
    asm volatile("cp.async.cg.shared.global [%0], [%1], 16;" :: "r"(dst), "l"(src));
}
#define CP_COMMIT() asm volatile("cp.async.commit_group;" ::: "memory")
#define CP_WAIT1()  asm volatile("cp.async.wait_group 1;" ::: "memory")
#define CP_WAIT0()  asm volatile("cp.async.wait_group 0;" ::: "memory")

__device__ __forceinline__ void ldsm4(uint32_t (&r)[4], uint32_t addr) {
    asm volatile("ldmatrix.sync.aligned.m8n8.x4.shared.b16 {%0,%1,%2,%3}, [%4];"
        : "=r"(r[0]), "=r"(r[1]), "=r"(r[2]), "=r"(r[3]) : "r"(addr));
}
__device__ __forceinline__ void mma_bf16(float* d, const uint32_t* a, uint32_t b0, uint32_t b1) {
    asm volatile("mma.sync.aligned.m16n8k16.row.col.f32.bf16.bf16.f32 "
        "{%0,%1,%2,%3}, {%4,%5,%6,%7}, {%8,%9}, {%0,%1,%2,%3};"
        : "+f"(d[0]), "+f"(d[1]), "+f"(d[2]), "+f"(d[3])
        : "r"(a[0]), "r"(a[1]), "r"(a[2]), "r"(a[3]), "r"(b0), "r"(b1));
}
__device__ __forceinline__ void split2(float a, float b, uint32_t& hi, uint32_t& lo) {
    __nv_bfloat16 ah = __float2bfloat16_rn(a);
    __nv_bfloat16 bh = __float2bfloat16_rn(b);
    __nv_bfloat16 al = __float2bfloat16_rn(a - __bfloat162float(ah));
    __nv_bfloat16 bl = __float2bfloat16_rn(b - __bfloat162float(bh));
    hi = (uint32_t)__bfloat16_as_ushort(ah) | ((uint32_t)__bfloat16_as_ushort(bh) << 16);
    lo = (uint32_t)__bfloat16_as_ushort(al) | ((uint32_t)__bfloat16_as_ushort(bl) << 16);
}

// Per-lane ldmatrix offsets (plane-relative, swizzled). [operand][ks]
struct FragOff { uint32_t a[4][2]; uint32_t b[2][2]; };
__device__ __forceinline__ void frag_offsets(int lane, int warp_m, int warp_n, FragOff& F) {
    int ha = lane >> 4;                      // A k-half (0/1)
#pragma unroll
    for (int wm = 0; wm < 4; wm++) {
        int row = warp_m * 64 + wm * 16 + (lane & 15);
        int x = (row >> 1) & 3;
#pragma unroll
        for (int ks = 0; ks < 2; ks++)
            F.a[wm][ks] = (uint32_t)(row * ROW64 + (((ks * 2 + ha) ^ x) << 4));
    }
    int rb = (lane & 7) + ((lane >> 4) << 3);
    int hb = (lane & 8) ? 1 : 0;             // B k-half
#pragma unroll
    for (int p = 0; p < 2; p++) {
        int row = warp_n * 32 + p * 16 + rb;
        int x = (row >> 1) & 3;
#pragma unroll
        for (int ks = 0; ks < 2; ks++)
            F.b[p][ks] = (uint32_t)(row * ROW64 + (((ks * 2 + hb) ^ x) << 4));
    }
}

// Issue cp.async for one BK=32 chunk into the given stage base (swizzled dst)
__device__ __forceinline__ void issue_cp(uint32_t sbase,
    const __nv_bfloat16* __restrict__ Ahi, const __nv_bfloat16* __restrict__ Alo, int lda,
    const __nv_bfloat16* __restrict__ Bhi, const __nv_bfloat16* __restrict__ Blo, int ldb,
    int k0, int tid)
{
    const int lrow = tid >> 1;
    const int c0 = (tid & 1) * 2;
    const int x = (lrow >> 1) & 3;
    const int koff = k0 + (tid & 1) * 16;
    uint32_t d0 = sbase + (uint32_t)(lrow * ROW64 + ((c0 ^ x) << 4));
    uint32_t d1 = sbase + (uint32_t)(lrow * ROW64 + (((c0 + 1) ^ x) << 4));
    const __nv_bfloat16* a0 = Ahi + (size_t)lrow * lda + koff;
    const __nv_bfloat16* a1 = Alo + (size_t)lrow * lda + koff;
    const __nv_bfloat16* b0 = Bhi + (size_t)lrow * ldb + koff;
    const __nv_bfloat16* b1 = Blo + (size_t)lrow * ldb + koff;
    cp16(d0, a0);               cp16(d1, a0 + 8);
    cp16(d0 + PLANE, a1);       cp16(d1 + PLANE, a1 + 8);
    cp16(d0 + 2 * PLANE, b0);   cp16(d1 + 2 * PLANE, b0 + 8);
    cp16(d0 + 3 * PLANE, b1);   cp16(d1 + 3 * PLANE, b1 + 8);
}

// One BK=32 chunk of bf16x3 MMA
__device__ __forceinline__ void mma_chunk32(uint32_t sb, const FragOff& F, float (*acc)[4][4]) {
#pragma unroll
    for (int ks = 0; ks < 2; ks++) {
        uint32_t af[4][4], bh[2][4], bl[2][4];
#pragma unroll
        for (int wm = 0; wm < 4; wm++) ldsm4(af[wm], sb + F.a[wm][ks]);
#pragma unroll
        for (int p = 0; p < 2; p++) ldsm4(bh[p], sb + 2 * PLANE + F.b[p][ks]);
#pragma unroll
        for (int p = 0; p < 2; p++) ldsm4(bl[p], sb + 3 * PLANE + F.b[p][ks]);
#pragma unroll
        for (int wm = 0; wm < 4; wm++)
#pragma unroll
            for (int wn = 0; wn < 4; wn++) {
                mma_bf16(acc[wm][wn], af[wm], bh[wn >> 1][(wn & 1) * 2], bh[wn >> 1][(wn & 1) * 2 + 1]);
                mma_bf16(acc[wm][wn], af[wm], bl[wn >> 1][(wn & 1) * 2], bl[wn >> 1][(wn & 1) * 2 + 1]);
            }
#pragma unroll
        for (int wm = 0; wm < 4; wm++) ldsm4(af[wm], sb + PLANE + F.a[wm][ks]);
#pragma unroll
        for (int wm = 0; wm < 4; wm++)
#pragma unroll
            for (int wn = 0; wn < 4; wn++)
                mma_bf16(acc[wm][wn], af[wm], bh[wn >> 1][(wn & 1) * 2], bh[wn >> 1][(wn & 1) * 2 + 1]);
    }
}

// 3-stage pipelined bf16 GEMM core (acc += A * B^T over K)
__device__ __forceinline__ void gemm_core(uint32_t sb,
    const __nv_bfloat16* Ahi, const __nv_bfloat16* Alo, int lda,
    const __nv_bfloat16* Bhi, const __nv_bfloat16* Blo, int ldb,
    int K, int tid, const FragOff& F, float (*acc)[4][4])
{
    const int nch = K / BKC;
    issue_cp(sb, Ahi, Alo, lda, Bhi, Blo, ldb, 0, tid);
    CP_COMMIT();
    issue_cp(sb + STAGE, Ahi, Alo, lda, Bhi, Blo, ldb, BKC, tid);
    CP_COMMIT();
    uint32_t cur = 0, nxt2 = 2 * STAGE;
    for (int ch = 0; ch < nch; ch++) {
        if (ch < nch - 1) { CP_WAIT1(); } else { CP_WAIT0(); }
        __syncthreads();
        if (ch + 2 < nch) {
            issue_cp(sb + nxt2, Ahi, Alo, lda, Bhi, Blo, ldb, (ch + 2) * BKC, tid);
            CP_COMMIT();
        }
        mma_chunk32(sb + cur, F, acc);
        cur = (cur == (NSTAGE - 1) * STAGE) ? 0 : cur + STAGE;
        nxt2 = (nxt2 == (NSTAGE - 1) * STAGE) ? 0 : nxt2 + STAGE;
    }
    __syncthreads();
}

// ---------------------------------------------------------------------------
// Elementwise fp32 -> bf16 hi/lo split
// ---------------------------------------------------------------------------
__global__ void split_kernel(const float* __restrict__ in,
                             __nv_bfloat16* __restrict__ hi,
                             __nv_bfloat16* __restrict__ lo, int n4)
{
    int i = blockIdx.x * blockDim.x + threadIdx.x;
    if (i < n4) {
        float4 v = reinterpret_cast<const float4*>(in)[i];
        uint32_t h0, l0, h1, l1;
        split2(v.x, v.y, h0, l0);
        split2(v.z, v.w, h1, l1);
        reinterpret_cast<uint2*>(hi)[i] = make_uint2(h0, h1);
        reinterpret_cast<uint2*>(lo)[i] = make_uint2(l0, l1);
    }
}

// ---------------------------------------------------------------------------
// Mask transpose + prescale: mT[b][k][q] = bf16(-1e9 * mask[b][q][k])
// ---------------------------------------------------------------------------
__global__ __launch_bounds__(256)
void maskT_kernel(const int* __restrict__ mask, __nv_bfloat16* __restrict__ mT)
{
    __shared__ float t[32][33];
    const int b = blockIdx.z;
    const int q0 = blockIdx.y * 32, k0 = blockIdx.x * 32;
    const int* mb = mask + (size_t)b * SS * SS;
    __nv_bfloat16* ob = mT + (size_t)b * SS * SS;
#pragma unroll
    for (int i = 0; i < 4; i++) {
        int q = q0 + threadIdx.y + i * 8;
        t[threadIdx.y + i * 8][threadIdx.x] =
            -1e9f * (float)mb[(size_t)q * SS + k0 + threadIdx.x];
    }
    __syncthreads();
#pragma unroll
    for (int i = 0; i < 4; i++) {
        int k = k0 + threadIdx.y + i * 8;
        ob[(size_t)k * SS + q0 + threadIdx.x] =
            __float2bfloat16_rn(t[threadIdx.x][threadIdx.y + i * 8]);
    }
}

// ---------------------------------------------------------------------------
// Projection: C[M,512] = A[M,1024]*W[512,1024]^T + bias -> bf16 hi/lo
// transpose=1 (V): writes WVT[b][n][s] via smem transpose.
// ---------------------------------------------------------------------------
__global__ __launch_bounds__(256, 2)
void proj_kernel(const __nv_bfloat16* __restrict__ Ahi, const __nv_bfloat16* __restrict__ Alo,
                 const __nv_bfloat16* __restrict__ Whi, const __nv_bfloat16* __restrict__ Wlo,
                 const float* __restrict__ bias,
                 __nv_bfloat16* __restrict__ Chi, __nv_bfloat16* __restrict__ Clo,
                 int transpose)
{
    extern __shared__ char smem[];
    uint32_t sb = smem_u32(smem);
    const int tid = threadIdx.x, lane = tid & 31, wid = tid >> 5;
    const int warp_m = wid & 1, warp_n = wid >> 1;
    const int m0 = blockIdx.y * BM, n0 = blockIdx.x * BN;

    float acc[4][4][4];
#pragma unroll
    for (int i = 0; i < 4; i++)
#pragma unroll
        for (int j = 0; j < 4; j++)
#pragma unroll
            for (int r = 0; r < 4; r++) acc[i][j][r] = 0.f;

    FragOff F;
    frag_offsets(lane, warp_m, warp_n, F);

    gemm_core(sb, Ahi + (size_t)m0 * DD, Alo + (size_t)m0 * DD, DD,
              Whi + (size_t)n0 * DD, Wlo + (size_t)n0 * DD, DD,
              DD, tid, F, acc);

    if (!transpose) {
#pragma unroll
        for (int wn = 0; wn < 4; wn++) {
            int n = n0 + warp_n * 32 + wn * 8 + (lane & 3) * 2;
            float b0 = bias[n], b1 = bias[n + 1];
#pragma unroll
            for (int wm = 0; wm < 4; wm++)
#pragma unroll
                for (int h = 0; h < 2; h++) {
                    int m = m0 + warp_m * 64 + wm * 16 + (lane >> 2) + h * 8;
                    uint32_t hv, lv;
                    split2(acc[wm][wn][h * 2] + b0, acc[wm][wn][h * 2 + 1] + b1, hv, lv);
                    *reinterpret_cast<uint32_t*>(Chi + (size_t)m * AA + n) = hv;
                    *reinterpret_cast<uint32_t*>(Clo + (size_t)m * AA + n) = lv;
                }
        }
    } else {
        char* T = smem;   // stride 272B rows; hi plane at 0, lo plane at 34816
#pragma unroll
        for (int wn = 0; wn < 4; wn++) {
            int ln = warp_n * 32 + wn * 8 + (lane & 3) * 2;
            float b0 = bias[n0 + ln], b1 = bias[n0 + ln + 1];
#pragma unroll
            for (int wm = 0; wm < 4; wm++)
#pragma unroll
                for (int h = 0; h < 2; h++) {
                    int lm = warp_m * 64 + wm * 16 + (lane >> 2) + h * 8;
                    float v0 = acc[wm][wn][h * 2] + b0;
                    float v1 = acc[wm][wn][h * 2 + 1] + b1;
                    __nv_bfloat16 h0 = __float2bfloat16_rn(v0);
                    __nv_bfloat16 l0 = __float2bfloat16_rn(v0 - __bfloat162float(h0));
                    __nv_bfloat16 h1 = __float2bfloat16_rn(v1);
                    __nv_bfloat16 l1 = __float2bfloat16_rn(v1 - __bfloat162float(h1));
                    *reinterpret_cast<__nv_bfloat16*>(T + ln * 272 + lm * 2) = h0;
                    *reinterpret_cast<__nv_bfloat16*>(T + (ln + 1) * 272 + lm * 2) = h1;
                    *reinterpret_cast<__nv_bfloat16*>(T + 34816 + ln * 272 + lm * 2) = l0;
                    *reinterpret_cast<__nv_bfloat16*>(T + 34816 + (ln + 1) * 272 + lm * 2) = l1;
                }
        }
        __syncthreads();
        int v = tid >> 1, hs = (tid & 1) * 64;
        size_t b = (size_t)(m0 >> 11);
        int s0 = m0 & (SS - 1);
        __nv_bfloat16* dh = Chi + (b * DVV + n0 + v) * SS + s0 + hs;
        __nv_bfloat16* dl = Clo + (b * DVV + n0 + v) * SS + s0 + hs;
#pragma unroll
        for (int g = 0; g < 8; g++) {
            *reinterpret_cast<uint4*>(dh + g * 8) =
                *reinterpret_cast<uint4*>(T + v * 272 + (hs + g * 8) * 2);
            *reinterpret_cast<uint4*>(dl + g * 8) =
                *reinterpret_cast<uint4*>(T + 34816 + v * 272 + (hs + g * 8) * 2);
        }
    }
}

// ---------------------------------------------------------------------------
// Scores (pre-transposed): attn[b][k][q] = scale*Kp[k]·Qp[q] + mT[b][k][q]
// ---------------------------------------------------------------------------
__global__ __launch_bounds__(256, 2)
void scores_kernel(const __nv_bfloat16* __restrict__ KpHi, const __nv_bfloat16* __restrict__ KpLo,
                   const __nv_bfloat16* __restrict__ QpHi, const __nv_bfloat16* __restrict__ QpLo,
                   const __nv_bfloat16* __restrict__ mT, float* __restrict__ attn)
{
    extern __shared__ char smem[];
    uint32_t sb = smem_u32(smem);
    const int tid = threadIdx.x, lane = tid & 31, wid = tid >> 5;
    const int warp_m = wid & 1, warp_n = wid >> 1;
    const int m0 = blockIdx.y * BM, n0 = blockIdx.x * BN, b = blockIdx.z;

    float acc[4][4][4];
#pragma unroll
    for (int i = 0; i < 4; i++)
#pragma unroll
        for (int j = 0; j < 4; j++)
#pragma unroll
            for (int r = 0; r < 4; r++) acc[i][j][r] = 0.f;

    FragOff F;
    frag_offsets(lane, warp_m, warp_n, F);

    const size_t base = (size_t)b * SS * AA;
    gemm_core(sb, KpHi + base + (size_t)m0 * AA, KpLo + base + (size_t)m0 * AA, AA,
              QpHi + base + (size_t)n0 * AA, QpLo + base + (size_t)n0 * AA, AA,
              AA, tid, F, acc);

    const float scale = 0.04419417382415922f;   // 1/sqrt(512)
    const __nv_bfloat16* mb = mT + (size_t)b * SS * SS;
    float* ab = attn + (size_t)b * SS * SS;
#pragma unroll
    for (int wm = 0; wm < 4; wm++)
#pragma unroll
        for (int h = 0; h < 2; h++) {
            int k = m0 + warp_m * 64 + wm * 16 + (lane >> 2) + h * 8;
#pragma unroll
            for (int wn = 0; wn < 4; wn++) {
                int q = n0 + warp_n * 32 + wn * 8 + (lane & 3) * 2;
                uint32_t mu = *reinterpret_cast<const uint32_t*>(mb + (size_t)k * SS + q);
                float mv0 = __bfloat162float(__ushort_as_bfloat16((unsigned short)(mu & 0xFFFF)));
                float mv1 = __bfloat162float(__ushort_as_bfloat16((unsigned short)(mu >> 16)));
                *reinterpret_cast<float2*>(ab + (size_t)k * SS + q) =
                    make_float2(fmaf(acc[wm][wn][h * 2], scale, mv0),
                                fmaf(acc[wm][wn][h * 2 + 1], scale, mv1));
            }
        }
}

// ---------------------------------------------------------------------------
// Output: out[b][k][v] = sum_q attn[b][k][q] * WVT[b][v][q]
// ---------------------------------------------------------------------------
__global__ __launch_bounds__(256, 2)
void out_kernel(const __nv_bfloat16* __restrict__ AtHi, const __nv_bfloat16* __restrict__ AtLo,
                const __nv_bfloat16* __restrict__ WVTHi, const __nv_bfloat16* __restrict__ WVTLo,
                float* __restrict__ out)
{
    extern __shared__ char smem[];
    uint32_t sb = smem_u32(smem);
    const int tid = threadIdx.x, lane = tid & 31, wid = tid >> 5;
    const int warp_m = wid & 1, warp_n = wid >> 1;
    const int m0 = blockIdx.y * BM, n0 = blockIdx.x * BN, b = blockIdx.z;

    float acc[4][4][4];
#pragma unroll
    for (int i = 0; i < 4; i++)
#pragma unroll
        for (int j = 0; j < 4; j++)
#pragma unroll
            for (int r = 0; r < 4; r++) acc[i][j][r] = 0.f;

    FragOff F;
    frag_offsets(lane, warp_m, warp_n, F);

    const size_t abase = (size_t)b * SS * SS;
    const size_t bbase = (size_t)b * DVV * SS;
    gemm_core(sb, AtHi + abase + (size_t)m0 * SS, AtLo + abase + (size_t)m0 * SS, SS,
              WVTHi + bbase + (size_t)n0 * SS, WVTLo + bbase + (size_t)n0 * SS, SS,
              SS, tid, F, acc);

    float* ob = out + (size_t)b * SS * DVV;
#pragma unroll
    for (int wm = 0; wm < 4; wm++)
#pragma unroll
        for (int h = 0; h < 2; h++) {
            int m = m0 + warp_m * 64 + wm * 16 + (lane >> 2) + h * 8;
#pragma unroll
            for (int wn = 0; wn < 4; wn++) {
                int n = n0 + warp_n * 32 + wn * 8 + (lane & 3) * 2;
                *reinterpret_cast<float2*>(ob + (size_t)m * DVV + n) =
                    make_float2(acc[wm][wn][h * 2], acc[wm][wn][h * 2 + 1]);
            }
        }
}

// ---------------------------------------------------------------------------
// In-place row softmax (fp32) + bf16 hi/lo split write for the out GEMM.
// ---------------------------------------------------------------------------
__global__ void softmax_rows(float* __restrict__ p,
                             __nv_bfloat16* __restrict__ hi,
                             __nv_bfloat16* __restrict__ lo)
{
    __shared__ float red[33];
    size_t rb = (size_t)blockIdx.x * SS;
    float* x = p + rb;
    int tid = threadIdx.x;
    float v[8];
    float mx = -1e30f;
#pragma unroll
    for (int i = 0; i < 8; i++) { v[i] = x[tid + i * 256]; mx = fmaxf(mx, v[i]); }
#pragma unroll
    for (int o = 16; o > 0; o >>= 1) mx = fmaxf(mx, __shfl_xor_sync(0xffffffffu, mx, o));
    if ((tid & 31) == 0) red[tid >> 5] = mx;
    __syncthreads();
    if (tid < 32) {
        float m = (tid < 8) ? red[tid] : -1e30f;
#pragma unroll
        for (int o = 4; o > 0; o >>= 1) m = fmaxf(m, __shfl_xor_sync(0xffffffffu, m, o));
        if (tid == 0) red[32] = m;
    }
    __syncthreads();
    mx = red[32];
    float s = 0.f;
#pragma unroll
    for (int i = 0; i < 8; i++) { v[i] = __expf(v[i] - mx); s += v[i]; }
#pragma unroll
    for (int o = 16; o > 0; o >>= 1) s += __shfl_xor_sync(0xffffffffu, s, o);
    if ((tid & 31) == 0) red[tid >> 5] = s;
    __syncthreads();
    if (tid < 32) {
        float m = (tid < 8) ? red[tid] : 0.f;
#pragma unroll
        for (int o = 4; o > 0; o >>= 1) m += __shfl_xor_sync(0xffffffffu, m, o);
        if (tid == 0) red[32] = m;
    }
    __syncthreads();
    float inv = 1.0f / red[32];
#pragma unroll
    for (int i = 0; i < 8; i++) {
        int idx = tid + i * 256;
        float val = v[i] * inv;
        x[idx] = val;
        __nv_bfloat16 h = __float2bfloat16_rn(val);
        hi[rb + idx] = h;
        lo[rb + idx] = __float2bfloat16_rn(val - __bfloat162float(h));
    }
}

// ---------------------------------------------------------------------------
extern "C" void kernel_launch(void* const* d_in, const int* in_sizes, int n_in,
                              void* d_out, int out_size)
{
    const float* Q    = (const float*)d_in[0];
    const float* K    = (const float*)d_in[1];
    const float* V    = (const float*)d_in[2];
    const int*   mask = (const int*)  d_in[3];
    const float* Wq   = (const float*)d_in[4];
    const float* bq   = (const float*)d_in[5];
    const float* Wk   = (const float*)d_in[6];
    const float* bk   = (const float*)d_in[7];
    const float* Wv   = (const float*)d_in[8];
    const float* bv   = (const float*)d_in[9];

    float* out  = (float*)d_out;                   // selfOutput [B,S,Dv]
    float* attn = out + (size_t)NB * SS * DVV;     // attn       [B,S,S]

    static __nv_bfloat16 *pQbHi, *pQbLo, *pKbHi, *pKbLo, *pVbHi, *pVbLo;
    static __nv_bfloat16 *pWqHi, *pWqLo, *pWkHi, *pWkLo, *pWvHi, *pWvLo;
    static __nv_bfloat16 *pQpHi, *pQpLo, *pKpHi, *pKpLo, *pWVTHi, *pWVTLo;
    static __nv_bfloat16 *pAtHi, *pAtLo, *pMkT;
    static bool inited = false;
    if (!inited) {
        cudaGetSymbolAddress((void**)&pQbHi, g_QbHi);   cudaGetSymbolAddress((void**)&pQbLo, g_QbLo);
        cudaGetSymbolAddress((void**)&pKbHi, g_KbHi);   cudaGetSymbolAddress((void**)&pKbLo, g_KbLo);
        cudaGetSymbolAddress((void**)&pVbHi, g_VbHi);   cudaGetSymbolAddress((void**)&pVbLo, g_VbLo);
        cudaGetSymbolAddress((void**)&pWqHi, g_WqHi);   cudaGetSymbolAddress((void**)&pWqLo, g_WqLo);
        cudaGetSymbolAddress((void**)&pWkHi, g_WkHi);   cudaGetSymbolAddress((void**)&pWkLo, g_WkLo);
        cudaGetSymbolAddress((void**)&pWvHi, g_WvHi);   cudaGetSymbolAddress((void**)&pWvLo, g_WvLo);
        cudaGetSymbolAddress((void**)&pQpHi, g_QpHi);   cudaGetSymbolAddress((void**)&pQpLo, g_QpLo);
        cudaGetSymbolAddress((void**)&pKpHi, g_KpHi);   cudaGetSymbolAddress((void**)&pKpLo, g_KpLo);
        cudaGetSymbolAddress((void**)&pWVTHi, g_WVTHi); cudaGetSymbolAddress((void**)&pWVTLo, g_WVTLo);
        cudaGetSymbolAddress((void**)&pAtHi, g_AtHi);   cudaGetSymbolAddress((void**)&pAtLo, g_AtLo);
        cudaGetSymbolAddress((void**)&pMkT, g_MkT);
        cudaFuncSetAttribute(proj_kernel,   cudaFuncAttributeMaxDynamicSharedMemorySize, SMEM_PIPE);
        cudaFuncSetAttribute(scores_kernel, cudaFuncAttributeMaxDynamicSharedMemorySize, SMEM_PIPE);
        cudaFuncSetAttribute(out_kernel,    cudaFuncAttributeMaxDynamicSharedMemorySize, SMEM_PIPE);
        inited = true;
    }

    // 1) Pre-split fp32 inputs to bf16 hi/lo
    {
        int n4 = (NB * SS * DD) / 4;
        int g = (n4 + 255) / 256;
        split_kernel<<<g, 256>>>(Q, pQbHi, pQbLo, n4);
        split_kernel<<<g, 256>>>(K, pKbHi, pKbLo, n4);
        split_kernel<<<g, 256>>>(V, pVbHi, pVbLo, n4);
        int w4 = (AA * DD) / 4;
        int gw = (w4 + 255) / 256;
        split_kernel<<<gw, 256>>>(Wq, pWqHi, pWqLo, w4);
        split_kernel<<<gw, 256>>>(Wk, pWkHi, pWkLo, w4);
        split_kernel<<<gw, 256>>>(Wv, pWvHi, pWvLo, w4);
    }
    // 2) Mask transpose + prescale
    maskT_kernel<<<dim3(SS / 32, SS / 32, NB), dim3(32, 8)>>>(mask, pMkT);

    dim3 blk(256);
    // 3) Projections: M = 16384, N = 512, K = 1024
    proj_kernel<<<dim3(4, 128), blk, SMEM_PIPE>>>(pQbHi, pQbLo, pWqHi, pWqLo, bq, pQpHi, pQpLo, 0);
    proj_kernel<<<dim3(4, 128), blk, SMEM_PIPE>>>(pKbHi, pKbLo, pWkHi, pWkLo, bk, pKpHi, pKpLo, 0);
    proj_kernel<<<dim3(4, 128), blk, SMEM_PIPE>>>(pVbHi, pVbLo, pWvHi, pWvLo, bv, pWVTHi, pWVTLo, 1);
    // 4) Masked, pre-transposed scores -> attn (fp32, in d_out)
    scores_kernel<<<dim3(16, 16, NB), blk, SMEM_PIPE>>>(pKpHi, pKpLo, pQpHi, pQpLo, pMkT, attn);
    // 5) Row softmax in place + bf16 hi/lo side-write
    softmax_rows<<<NB * SS, 256>>>(attn, pAtHi, pAtLo);
    // 6) selfOutput = attn @ WV  (K = 2048)
    out_kernel<<<dim3(4, 16, NB), blk, SMEM_PIPE>>>(pAtHi, pAtLo, pWVTHi, pWVTLo, out);
}